// round 14
// baseline (speedup 1.0000x reference)
#include <cuda_runtime.h>
#include <cstdint>
#include <math.h>

#define DIM   8192
#define BATCH 8
#define TOPK  60
#define CHUNK 2048             // dense-GEMV k-chunk staged in smem
#define NCHUNK (DIM / CHUNK)   // 4
#define DENSE_SMEM (4 * CHUNK * 8)   // 64 KB
#define NBINS 2048
#define CCAP  128              // candidate cap before fallback
#define TK_THREADS 1024

// prefilter ladder (float bits); all >= 0.5 so (bits-TH)>>12 < 2048
#define TH0 0x3F000000u   // 0.5
#define TH1 0x3F040000u   // ~0.5156
#define TH2 0x3F080000u   // ~0.5313
#define TH3 0x3F400000u   // 0.75
#define TH4 0x3F600000u   // 0.875
#define TH5 0x3F700000u   // 0.9375

typedef unsigned long long ull;
typedef unsigned int uint;

// ---------------- device scratch (no allocations allowed) ----------------
__device__ float g_act[BATCH * DIM];               // step-1 sigmoid output
__device__ float g_z2 [BATCH * DIM];               // step-2 sigmoid output
__device__ float g_vals[BATCH * 64];               // top-k values, idx-sorted, 0-padded to 64
__device__ int   g_idxs[BATCH * 64];               // top-k indices, ascending, 0-padded

// ---------------- helpers ----------------
__device__ __forceinline__ float sigmoidf(float x) {
    return 1.0f / (1.0f + expf(-x));   // precise expf: selection must match reference
}
__device__ __forceinline__ ull pack2(float x, float y) {
    ull r; asm("mov.b64 %0, {%1,%2};" : "=l"(r) : "f"(x), "f"(y)); return r;
}
__device__ __forceinline__ void unpack2(ull v, float &x, float &y) {
    asm("mov.b64 {%0,%1}, %2;" : "=f"(x), "=f"(y) : "l"(v));
}
__device__ __forceinline__ void fma2(ull &d, ull a, ull b) {
    asm("fma.rn.f32x2 %0, %1, %2, %0;" : "+l"(d) : "l"(a), "l"(b));
}
__device__ __forceinline__ int warp_sum(int c) {
#pragma unroll
    for (int o = 16; o > 0; o >>= 1) c += __shfl_xor_sync(0xFFFFFFFFu, c, o);
    return c;
}

// ---------------- kernel 1: dense GEMV-8 + sigmoid, smem-staged sdr ----------------
__global__ __launch_bounds__(256, 2) void gemv_dense_kernel(
        const float* __restrict__ syn, const float* __restrict__ sdr) {
    extern __shared__ __align__(16) ull s_sdr[];   // [4][CHUNK]
    int tid  = threadIdx.x;
    int warp = blockIdx.x * 8 + (tid >> 5);        // 2048 warps
    int lane = tid & 31;
    int j0 = warp * 4;

    cudaTriggerProgrammaticLaunchCompletion();     // let topk0 spin up early

    const float4* r0 = (const float4*)(syn + (size_t)(j0 + 0) * DIM);
    const float4* r1 = (const float4*)(syn + (size_t)(j0 + 1) * DIM);
    const float4* r2 = (const float4*)(syn + (size_t)(j0 + 2) * DIM);
    const float4* r3 = (const float4*)(syn + (size_t)(j0 + 3) * DIM);

    ull acc[4][4];
#pragma unroll
    for (int i = 0; i < 4; i++)
#pragma unroll
        for (int p = 0; p < 4; p++) acc[i][p] = 0ull;

    for (int c = 0; c < NCHUNK; c++) {
        int g4 = c * CHUNK / 4;

        __syncthreads();
        for (int t4 = tid; t4 < CHUNK / 4; t4 += 256) {
#pragma unroll
            for (int p = 0; p < 4; p++) {
                float4 lo = ((const float4*)(sdr + (size_t)(2 * p)     * DIM))[g4 + t4];
                float4 hi = ((const float4*)(sdr + (size_t)(2 * p + 1) * DIM))[g4 + t4];
                ull* d = &s_sdr[p * CHUNK + t4 * 4];
                d[0] = pack2(lo.x, hi.x);
                d[1] = pack2(lo.y, hi.y);
                d[2] = pack2(lo.z, hi.z);
                d[3] = pack2(lo.w, hi.w);
            }
        }
        __syncthreads();

        for (int t = 0; t < CHUNK / 4; t += 128) {
            float4 a0[4], a1[4], a2[4], a3[4];
#pragma unroll
            for (int u = 0; u < 4; u++) {
                int k4 = g4 + t + u * 32 + lane;
                a0[u] = r0[k4]; a1[u] = r1[k4]; a2[u] = r2[k4]; a3[u] = r3[k4];
            }
#pragma unroll
            for (int u = 0; u < 4; u++) {
                int kk = (t + u * 32 + lane) * 4;
                ulonglong2 sA[4], sB[4];
#pragma unroll
                for (int p = 0; p < 4; p++) {
                    const ulonglong2* sp = (const ulonglong2*)&s_sdr[p * CHUNK + kk];
                    sA[p] = sp[0];
                    sB[p] = sp[1];
                }
#pragma unroll
                for (int i = 0; i < 4; i++) {
                    float4 a = (i == 0 ? a0[u] : i == 1 ? a1[u] : i == 2 ? a2[u] : a3[u]);
                    ull px = pack2(a.x, a.x), py = pack2(a.y, a.y);
                    ull pz = pack2(a.z, a.z), pw = pack2(a.w, a.w);
#pragma unroll
                    for (int p = 0; p < 4; p++) {
                        fma2(acc[i][p], px, sA[p].x);
                        fma2(acc[i][p], py, sA[p].y);
                        fma2(acc[i][p], pz, sB[p].x);
                        fma2(acc[i][p], pw, sB[p].y);
                    }
                }
            }
        }
    }

#pragma unroll
    for (int i = 0; i < 4; i++) {
#pragma unroll
        for (int p = 0; p < 4; p++) {
            float x, y;
            unpack2(acc[i][p], x, y);
#pragma unroll
            for (int o = 16; o > 0; o >>= 1) {
                x += __shfl_down_sync(0xFFFFFFFFu, x, o);
                y += __shfl_down_sync(0xFFFFFFFFu, y, o);
            }
            if (lane == 0) {
                g_act[(size_t)(2 * p)     * DIM + (j0 + i)] = sigmoidf(x);
                g_act[(size_t)(2 * p + 1) * DIM + (j0 + i)] = sigmoidf(y);
            }
        }
    }
}

// ---------------- kernel 2/4: per-row top-k, adaptive-prefilter histogram ----------------
// Count pass picks the tightest ladder threshold with >= TOPK values above it,
// so the histogram only touches a few hundred values (smem ATOMS was the old cost).
// Exact jax.lax.top_k tie semantics (lowest index wins at the cutoff).
__global__ __launch_bounds__(TK_THREADS) void topk_kernel(float* __restrict__ full_out, int phase) {
    int b    = blockIdx.x;
    int tid  = threadIdx.x;
    int lane = tid & 31;
    int wid  = tid >> 5;

    __shared__ uint  s_h[NBINS];
    __shared__ int   s_tc[6];
    __shared__ int   s_wsum[32], s_wsuf[32];
    __shared__ int   s_B, s_cntgt, s_nc;
    __shared__ uint  s_Tsh;
    __shared__ int   s_nselsh;
    __shared__ uint  s_cb[CCAP];
    __shared__ int   s_cp[CCAP];
    __shared__ int   s_tie[64];
    __shared__ float s_outv[64];
    __shared__ int   s_outi[64];
    __shared__ int   s_cnt[40];
    __shared__ int   s_ntie, s_slot;

    cudaTriggerProgrammaticLaunchCompletion();     // let the next kernel spin up

    // non-dependent prologue: zero smem
#pragma unroll
    for (int q = 0; q < NBINS / TK_THREADS; q++) s_h[q * TK_THREADS + tid] = 0u;
    if (tid < 40) s_cnt[tid] = 0;
    if (tid < 6)  s_tc[tid] = 0;
    if (tid == 0) { s_nc = 0; s_ntie = 0; s_slot = 0; }

    cudaGridDependencySynchronize();               // producer results now visible

    const float* row = (phase == 0 ? g_act : g_z2) + (size_t)b * DIM;
    const float4* row4 = (const float4*)row;

    uint ub[8];
#pragma unroll
    for (int i = 0; i < 2; i++) {
        float4 v = row4[i * TK_THREADS + tid];
        ub[i * 4 + 0] = __float_as_uint(v.x);
        ub[i * 4 + 1] = __float_as_uint(v.y);
        ub[i * 4 + 2] = __float_as_uint(v.z);
        ub[i * 4 + 3] = __float_as_uint(v.w);
    }
    __syncthreads();

    // multi-threshold count pass (no atomoch per value — 6 block counters)
    {
        int c0 = 0, c1 = 0, c2 = 0, c3 = 0, c4 = 0, c5 = 0;
#pragma unroll
        for (int i = 0; i < 8; i++) {
            uint u = ub[i];
            c0 += (u >= TH0); c1 += (u >= TH1); c2 += (u >= TH2);
            c3 += (u >= TH3); c4 += (u >= TH4); c5 += (u >= TH5);
        }
        c0 = warp_sum(c0); c1 = warp_sum(c1); c2 = warp_sum(c2);
        c3 = warp_sum(c3); c4 = warp_sum(c4); c5 = warp_sum(c5);
        if (lane == 0) {
            atomicAdd(&s_tc[0], c0); atomicAdd(&s_tc[1], c1);
            atomicAdd(&s_tc[2], c2); atomicAdd(&s_tc[3], c3);
            atomicAdd(&s_tc[4], c4); atomicAdd(&s_tc[5], c5);
        }
    }
    __syncthreads();

    // pick tightest threshold with count >= TOPK (uniform across block)
    bool primary = (s_tc[0] >= TOPK);
    uint TB = TH0;
    if (s_tc[1] >= TOPK) TB = TH1;
    if (s_tc[2] >= TOPK) TB = TH2;
    if (s_tc[3] >= TOPK) TB = TH3;
    if (s_tc[4] >= TOPK) TB = TH4;
    if (s_tc[5] >= TOPK) TB = TH5;

    uint T = 0;
    int  nsel = 0;

    if (primary) {
        // histogram only values >= TB (few hundred atomics per block)
#pragma unroll
        for (int i = 0; i < 8; i++) {
            if (ub[i] >= TB) {
                uint bin = min((uint)(NBINS - 1), (ub[i] - TB) >> 12);
                atomicAdd(&s_h[bin], 1u);
            }
        }
        __syncthreads();

        // suffix scan over 2048 bins (2 per thread)
        uint h0 = s_h[tid * 2 + 0], h1 = s_h[tid * 2 + 1];
        int local = (int)(h0 + h1);
        int x = local;
#pragma unroll
        for (int o = 1; o < 32; o <<= 1) {
            int v = __shfl_down_sync(0xFFFFFFFFu, x, o);
            if (lane + o < 32) x += v;
        }
        if (lane == 0) s_wsum[wid] = x;        // warp total
        __syncthreads();
        if (wid == 0) {
            int w = s_wsum[lane];
#pragma unroll
            for (int o = 1; o < 32; o <<= 1) {
                int v = __shfl_down_sync(0xFFFFFFFFu, w, o);
                if (lane + o < 32) w += v;
            }
            s_wsuf[lane] = w;                  // suffix over warps >= lane
        }
        __syncthreads();

        int incl = x + ((wid < 31) ? s_wsuf[wid + 1] : 0);
        int excl = incl - local;
        int c1b = excl + (int)h1;
        int c0b = c1b + (int)h0;
        if (c0b >= TOPK && c1b < TOPK)  { s_B = tid * 2 + 0; s_cntgt = c1b; }
        if (c1b >= TOPK && excl < TOPK) { s_B = tid * 2 + 1; s_cntgt = excl; }
        __syncthreads();
        int B = s_B, cnt_gt = s_cntgt;

        // gather candidates in bin B
#pragma unroll
        for (int i = 0; i < 8; i++) {
            if (ub[i] >= TB) {
                uint bin = min((uint)(NBINS - 1), (ub[i] - TB) >> 12);
                if ((int)bin == B) {
                    int t = atomicAdd(&s_nc, 1);
                    if (t < CCAP) {
                        s_cb[t] = ub[i];
                        s_cp[t] = (i >> 2) * 4096 + tid * 4 + (i & 3);
                    }
                }
            }
        }
        __syncthreads();
        int nc = s_nc;
        if (nc <= CCAP) {
            if (tid == 0) {
                for (int q = 1; q < nc; q++) {       // bits desc, pos asc on ties
                    uint vb = s_cb[q]; int vp = s_cp[q];
                    int y = q - 1;
                    while (y >= 0 && (s_cb[y] < vb || (s_cb[y] == vb && s_cp[y] > vp))) {
                        s_cb[y + 1] = s_cb[y]; s_cp[y + 1] = s_cp[y]; y--;
                    }
                    s_cb[y + 1] = vb; s_cp[y + 1] = vp;
                }
                int need = TOPK - cnt_gt;
                uint Tv = s_cb[need - 1];
                int first = 0;
                while (s_cb[first] != Tv) first++;
                int ns = need - first;
                if (ns > 64) ns = 64;
                for (int q = 0; q < ns; q++) s_tie[q] = s_cp[first + q];
                s_Tsh = Tv;
                s_nselsh = ns;
            }
            __syncthreads();
            T = s_Tsh;
            nsel = s_nselsh;
        } else {
            primary = false;
        }
    }

    if (!primary) {
        // fallback: binary search over float bits + tie machinery
        uint lo = 0u, hi = 0x3F800001u;
        int it = 0;
        while (hi - lo > 1u) {
            uint mid = lo + ((hi - lo) >> 1);
            int c = 0;
#pragma unroll
            for (int i = 0; i < 8; i++) c += (ub[i] >= mid);
            c = warp_sum(c);
            if (lane == 0) atomicAdd(&s_cnt[it], c);
            __syncthreads();
            int tot = s_cnt[it];
            it++;
            if (tot >= TOPK) lo = mid; else hi = mid;
        }
        T = lo;
        {
            int c = 0;
#pragma unroll
            for (int i = 0; i < 8; i++) c += (ub[i] > T);
            c = warp_sum(c);
            if (lane == 0) atomicAdd(&s_cnt[33], c);
        }
#pragma unroll
        for (int i = 0; i < 8; i++) {
            if (ub[i] == T) {
                int pos = (i >> 2) * 4096 + tid * 4 + (i & 3);
                int t = atomicAdd(&s_ntie, 1);
                if (t < 64) s_tie[t] = pos;
            }
        }
        __syncthreads();
        int cnt_gt = s_cnt[33];
        int needed = TOPK - cnt_gt;
        int ntie = min(s_ntie, 64);
        if (tid == 0) {
            for (int q = 1; q < ntie; q++) {
                int v = s_tie[q], y = q - 1;
                while (y >= 0 && s_tie[y] > v) { s_tie[y + 1] = s_tie[y]; y--; }
                s_tie[y + 1] = v;
            }
        }
        __syncthreads();
        nsel = min(needed, 64);
    }

    // ---- selection pass ----
    if (phase == 1) {
        // full-row coalesced write: (take ? val : 0) for every element
        float out[8];
#pragma unroll
        for (int i = 0; i < 8; i++) {
            uint u = ub[i];
            int pos = (i >> 2) * 4096 + tid * 4 + (i & 3);
            bool take = (u > T);
            if (u == T) {
                for (int q = 0; q < nsel; q++) take |= (s_tie[q] == pos);
            }
            out[i] = take ? __uint_as_float(u) : 0.0f;
        }
        float4* o4 = (float4*)(full_out + (size_t)b * DIM);
        o4[tid]              = make_float4(out[0], out[1], out[2], out[3]);
        o4[TK_THREADS + tid] = make_float4(out[4], out[5], out[6], out[7]);
    } else {
#pragma unroll
        for (int i = 0; i < 8; i++) {
            uint u = ub[i];
            int pos = (i >> 2) * 4096 + tid * 4 + (i & 3);
            bool take = (u > T);
            if (u == T) {
                for (int q = 0; q < nsel; q++) take |= (s_tie[q] == pos);
            }
            if (take) {
                int slot = atomicAdd(&s_slot, 1);
                s_outv[slot] = __uint_as_float(u);
                s_outi[slot] = pos;
            }
        }
        __syncthreads();
        if (tid < TOPK) {
            int my_i = s_outi[tid];
            float my_v = s_outv[tid];
            int rank = 0;
#pragma unroll 10
            for (int q = 0; q < TOPK; q++) rank += (s_outi[q] < my_i);
            g_vals[b * 64 + rank] = my_v;
            g_idxs[b * 64 + rank] = my_i;
        } else if (tid < 64) {                 // pad entries: val 0, col 0
            g_vals[b * 64 + tid] = 0.0f;
            g_idxs[b * 64 + tid] = 0;
        }
    }
}

// ---------------- kernel 3: sparse GEMV, per-batch sorted sweep ----------------
__global__ __launch_bounds__(256) void gemv_sparse_kernel(const float* __restrict__ syn) {
    int tid  = threadIdx.x;
    int w    = tid >> 5;
    int lane = tid & 31;
    int j = blockIdx.x * 8 + w;

    __shared__ float sv[BATCH][64];
    __shared__ int   si[BATCH][64];

    cudaTriggerProgrammaticLaunchCompletion();     // let topk1 spin up
    cudaGridDependencySynchronize();               // topk0 results visible

    for (int t = tid; t < BATCH * 64; t += 256) {
        sv[t >> 6][t & 63] = g_vals[t];
        si[t >> 6][t & 63] = g_idxs[t];
    }
    __syncthreads();

    const float* __restrict__ row = syn + (size_t)j * DIM;
    float acc[BATCH];
#pragma unroll
    for (int b = 0; b < BATCH; b++) {
        acc[b] = sv[b][lane]      * __ldg(&row[si[b][lane]])
               + sv[b][lane + 32] * __ldg(&row[si[b][lane + 32]]);
    }

#pragma unroll
    for (int o = 16; o > 0; o >>= 1) {
#pragma unroll
        for (int b = 0; b < BATCH; b++) {
            acc[b] += __shfl_down_sync(0xFFFFFFFFu, acc[b], o);
        }
    }
    float mine = 0.0f;
#pragma unroll
    for (int b = 0; b < BATCH; b++) {
        float r = __shfl_sync(0xFFFFFFFFu, acc[b], 0);
        if (lane == b) mine = r;
    }
    if (lane < BATCH) {
        g_z2[(size_t)lane * DIM + j] = sigmoidf(mine);
    }
}

// ---------------- launch ----------------
extern "C" void kernel_launch(void* const* d_in, const int* in_sizes, int n_in,
                              void* d_out, int out_size) {
    const float* sdr = (const float*)d_in[0];   // [8, 8192]
    const float* syn = (const float*)d_in[1];   // [8192, 8192]
    float* out = (float*)d_out;                 // [8, 8192]
    (void)in_sizes; (void)n_in; (void)out_size;

    static int smem_set = 0;
    if (!smem_set) {
        cudaFuncSetAttribute(gemv_dense_kernel,
                             cudaFuncAttributeMaxDynamicSharedMemorySize, DENSE_SMEM);
        smem_set = 1;
    }

    cudaLaunchAttribute pdl[1];
    pdl[0].id = cudaLaunchAttributeProgrammaticStreamSerialization;
    pdl[0].val.programmaticStreamSerializationAllowed = 1;

    {   // dense GEMV
        cudaLaunchConfig_t cfg = {};
        cfg.gridDim = dim3(DIM / 32, 1, 1);
        cfg.blockDim = dim3(256, 1, 1);
        cfg.dynamicSmemBytes = DENSE_SMEM;
        cfg.attrs = pdl; cfg.numAttrs = 1;
        cudaLaunchKernelEx(&cfg, gemv_dense_kernel, syn, sdr);
    }
    {   // topk phase 0
        cudaLaunchConfig_t cfg = {};
        cfg.gridDim = dim3(BATCH, 1, 1);
        cfg.blockDim = dim3(TK_THREADS, 1, 1);
        cfg.attrs = pdl; cfg.numAttrs = 1;
        cudaLaunchKernelEx(&cfg, topk_kernel, out, 0);
    }
    {   // sparse GEMV
        cudaLaunchConfig_t cfg = {};
        cfg.gridDim = dim3(DIM / 8, 1, 1);
        cfg.blockDim = dim3(256, 1, 1);
        cfg.attrs = pdl; cfg.numAttrs = 1;
        cudaLaunchKernelEx(&cfg, gemv_sparse_kernel, syn);
    }
    {   // topk phase 1
        cudaLaunchConfig_t cfg = {};
        cfg.gridDim = dim3(BATCH, 1, 1);
        cfg.blockDim = dim3(TK_THREADS, 1, 1);
        cfg.attrs = pdl; cfg.numAttrs = 1;
        cudaLaunchKernelEx(&cfg, topk_kernel, out, 1);
    }
}

// round 15
// speedup vs baseline: 1.0351x; 1.0351x over previous
#include <cuda_runtime.h>
#include <cstdint>
#include <math.h>

#define DIM   8192
#define BATCH 8
#define TOPK  60
#define CHUNK 2048             // dense-GEMV k-chunk staged in smem
#define NCHUNK (DIM / CHUNK)   // 4
#define DENSE_SMEM (4 * CHUNK * 8)   // 64 KB
#define NBINS 2048
#define CCAP  128              // candidate cap before fallback
#define TK_THREADS 1024

typedef unsigned long long ull;
typedef unsigned int uint;

// ---------------- device scratch (no allocations allowed) ----------------
__device__ float g_act[BATCH * DIM];               // step-1 sigmoid output
__device__ float g_z2 [BATCH * DIM];               // step-2 sigmoid output
__device__ float g_vals[BATCH * 64];               // top-k values, idx-sorted, 0-padded to 64
__device__ int   g_idxs[BATCH * 64];               // top-k indices, ascending, 0-padded

// ---------------- helpers ----------------
__device__ __forceinline__ float sigmoidf(float x) {
    return 1.0f / (1.0f + expf(-x));   // precise expf: selection must match reference
}
__device__ __forceinline__ ull pack2(float x, float y) {
    ull r; asm("mov.b64 %0, {%1,%2};" : "=l"(r) : "f"(x), "f"(y)); return r;
}
__device__ __forceinline__ void unpack2(ull v, float &x, float &y) {
    asm("mov.b64 {%0,%1}, %2;" : "=f"(x), "=f"(y) : "l"(v));
}
__device__ __forceinline__ void fma2(ull &d, ull a, ull b) {
    asm("fma.rn.f32x2 %0, %1, %2, %0;" : "+l"(d) : "l"(a), "l"(b));
}

// ---------------- kernel 1: dense GEMV-8 + sigmoid, smem-staged sdr ----------------
__global__ __launch_bounds__(256, 2) void gemv_dense_kernel(
        const float* __restrict__ syn, const float* __restrict__ sdr) {
    extern __shared__ __align__(16) ull s_sdr[];   // [4][CHUNK]
    int tid  = threadIdx.x;
    int warp = blockIdx.x * 8 + (tid >> 5);        // 2048 warps
    int lane = tid & 31;
    int j0 = warp * 4;

    cudaTriggerProgrammaticLaunchCompletion();     // let topk0 spin up early

    const float4* r0 = (const float4*)(syn + (size_t)(j0 + 0) * DIM);
    const float4* r1 = (const float4*)(syn + (size_t)(j0 + 1) * DIM);
    const float4* r2 = (const float4*)(syn + (size_t)(j0 + 2) * DIM);
    const float4* r3 = (const float4*)(syn + (size_t)(j0 + 3) * DIM);

    ull acc[4][4];
#pragma unroll
    for (int i = 0; i < 4; i++)
#pragma unroll
        for (int p = 0; p < 4; p++) acc[i][p] = 0ull;

    for (int c = 0; c < NCHUNK; c++) {
        int g4 = c * CHUNK / 4;

        __syncthreads();
        for (int t4 = tid; t4 < CHUNK / 4; t4 += 256) {
#pragma unroll
            for (int p = 0; p < 4; p++) {
                float4 lo = ((const float4*)(sdr + (size_t)(2 * p)     * DIM))[g4 + t4];
                float4 hi = ((const float4*)(sdr + (size_t)(2 * p + 1) * DIM))[g4 + t4];
                ull* d = &s_sdr[p * CHUNK + t4 * 4];
                d[0] = pack2(lo.x, hi.x);
                d[1] = pack2(lo.y, hi.y);
                d[2] = pack2(lo.z, hi.z);
                d[3] = pack2(lo.w, hi.w);
            }
        }
        __syncthreads();

        for (int t = 0; t < CHUNK / 4; t += 128) {
            float4 a0[4], a1[4], a2[4], a3[4];
#pragma unroll
            for (int u = 0; u < 4; u++) {
                int k4 = g4 + t + u * 32 + lane;
                a0[u] = r0[k4]; a1[u] = r1[k4]; a2[u] = r2[k4]; a3[u] = r3[k4];
            }
#pragma unroll
            for (int u = 0; u < 4; u++) {
                int kk = (t + u * 32 + lane) * 4;
                ulonglong2 sA[4], sB[4];
#pragma unroll
                for (int p = 0; p < 4; p++) {
                    const ulonglong2* sp = (const ulonglong2*)&s_sdr[p * CHUNK + kk];
                    sA[p] = sp[0];
                    sB[p] = sp[1];
                }
#pragma unroll
                for (int i = 0; i < 4; i++) {
                    float4 a = (i == 0 ? a0[u] : i == 1 ? a1[u] : i == 2 ? a2[u] : a3[u]);
                    ull px = pack2(a.x, a.x), py = pack2(a.y, a.y);
                    ull pz = pack2(a.z, a.z), pw = pack2(a.w, a.w);
#pragma unroll
                    for (int p = 0; p < 4; p++) {
                        fma2(acc[i][p], px, sA[p].x);
                        fma2(acc[i][p], py, sA[p].y);
                        fma2(acc[i][p], pz, sB[p].x);
                        fma2(acc[i][p], pw, sB[p].y);
                    }
                }
            }
        }
    }

#pragma unroll
    for (int i = 0; i < 4; i++) {
#pragma unroll
        for (int p = 0; p < 4; p++) {
            float x, y;
            unpack2(acc[i][p], x, y);
#pragma unroll
            for (int o = 16; o > 0; o >>= 1) {
                x += __shfl_down_sync(0xFFFFFFFFu, x, o);
                y += __shfl_down_sync(0xFFFFFFFFu, y, o);
            }
            if (lane == 0) {
                g_act[(size_t)(2 * p)     * DIM + (j0 + i)] = sigmoidf(x);
                g_act[(size_t)(2 * p + 1) * DIM + (j0 + i)] = sigmoidf(y);
            }
        }
    }
}

// ---------------- kernel 2/4: per-row top-k via histogram select ----------------
// PDL consumer: smem init runs pre-sync; row loads wait for the producer.
// Exact jax.lax.top_k tie semantics (lowest index wins at the cutoff).
__global__ __launch_bounds__(TK_THREADS) void topk_kernel(float* __restrict__ full_out, int phase) {
    int b    = blockIdx.x;
    int tid  = threadIdx.x;
    int lane = tid & 31;
    int wid  = tid >> 5;

    __shared__ uint  s_h[NBINS];
    __shared__ int   s_wsum[32], s_wsuf[32];
    __shared__ int   s_B, s_cntgt, s_nc;
    __shared__ uint  s_Tsh;
    __shared__ int   s_nselsh;
    __shared__ uint  s_cb[CCAP];
    __shared__ int   s_cp[CCAP];
    __shared__ int   s_tie[64];
    __shared__ float s_outv[64];
    __shared__ int   s_outi[64];
    __shared__ int   s_cnt[40];
    __shared__ int   s_ntie, s_slot;

    cudaTriggerProgrammaticLaunchCompletion();     // let the next kernel spin up

    // non-dependent prologue: zero smem
#pragma unroll
    for (int q = 0; q < NBINS / TK_THREADS; q++) s_h[q * TK_THREADS + tid] = 0u;
    if (tid < 40) s_cnt[tid] = 0;
    if (tid == 0) { s_nc = 0; s_ntie = 0; s_slot = 0; }

    cudaGridDependencySynchronize();               // producer results now visible

    const float* row = (phase == 0 ? g_act : g_z2) + (size_t)b * DIM;
    const float4* row4 = (const float4*)row;

    uint ub[8];
#pragma unroll
    for (int i = 0; i < 2; i++) {
        float4 v = row4[i * TK_THREADS + tid];
        ub[i * 4 + 0] = __float_as_uint(v.x);
        ub[i * 4 + 1] = __float_as_uint(v.y);
        ub[i * 4 + 2] = __float_as_uint(v.z);
        ub[i * 4 + 3] = __float_as_uint(v.w);
    }
    __syncthreads();

    // histogram the upper half (values >= 0.5)
#pragma unroll
    for (int i = 0; i < 8; i++) {
        if (ub[i] >= 0x3F000000u) {
            uint bin = min((uint)(NBINS - 1), (ub[i] - 0x3F000000u) >> 12);
            atomicAdd(&s_h[bin], 1u);
        }
    }
    __syncthreads();

    // suffix scan over 2048 bins (2 per thread); total falls out of the scan
    uint h0 = s_h[tid * 2 + 0], h1 = s_h[tid * 2 + 1];
    int local = (int)(h0 + h1);
    int x = local;
#pragma unroll
    for (int o = 1; o < 32; o <<= 1) {
        int v = __shfl_down_sync(0xFFFFFFFFu, x, o);
        if (lane + o < 32) x += v;
    }
    if (lane == 0) s_wsum[wid] = x;        // warp total
    __syncthreads();
    if (wid == 0) {
        int w = s_wsum[lane];
#pragma unroll
        for (int o = 1; o < 32; o <<= 1) {
            int v = __shfl_down_sync(0xFFFFFFFFu, w, o);
            if (lane + o < 32) w += v;
        }
        s_wsuf[lane] = w;                  // suffix over warps >= lane
    }
    __syncthreads();

    uint T = 0;
    int  nsel = 0;
    bool primary = (s_wsuf[0] >= TOPK);    // total count of values >= 0.5

    if (primary) {
        int incl = x + ((wid < 31) ? s_wsuf[wid + 1] : 0);
        int excl = incl - local;
        int c1 = excl + (int)h1;
        int c0 = c1 + (int)h0;
        if (c0 >= TOPK && c1 < TOPK)  { s_B = tid * 2 + 0; s_cntgt = c1; }
        if (c1 >= TOPK && excl < TOPK){ s_B = tid * 2 + 1; s_cntgt = excl; }
        __syncthreads();
        int B = s_B, cnt_gt = s_cntgt;

        // gather candidates in bin B
#pragma unroll
        for (int i = 0; i < 8; i++) {
            if (ub[i] >= 0x3F000000u) {
                uint bin = min((uint)(NBINS - 1), (ub[i] - 0x3F000000u) >> 12);
                if ((int)bin == B) {
                    int t = atomicAdd(&s_nc, 1);
                    if (t < CCAP) {
                        s_cb[t] = ub[i];
                        s_cp[t] = (i >> 2) * 4096 + tid * 4 + (i & 3);
                    }
                }
            }
        }
        __syncthreads();
        int nc = s_nc;
        if (nc <= CCAP) {
            if (tid == 0) {
                for (int q = 1; q < nc; q++) {       // bits desc, pos asc on ties
                    uint vb = s_cb[q]; int vp = s_cp[q];
                    int y = q - 1;
                    while (y >= 0 && (s_cb[y] < vb || (s_cb[y] == vb && s_cp[y] > vp))) {
                        s_cb[y + 1] = s_cb[y]; s_cp[y + 1] = s_cp[y]; y--;
                    }
                    s_cb[y + 1] = vb; s_cp[y + 1] = vp;
                }
                int need = TOPK - cnt_gt;
                uint Tv = s_cb[need - 1];
                int first = 0;
                while (s_cb[first] != Tv) first++;
                int ns = need - first;
                if (ns > 64) ns = 64;
                for (int q = 0; q < ns; q++) s_tie[q] = s_cp[first + q];
                s_Tsh = Tv;
                s_nselsh = ns;
            }
            __syncthreads();
            T = s_Tsh;
            nsel = s_nselsh;
        } else {
            primary = false;
        }
    } else {
        __syncthreads();                   // match primary-path barrier structure
    }

    if (!primary) {
        // fallback: binary search over float bits + tie machinery
        uint lo = 0u, hi = 0x3F800001u;
        int it = 0;
        while (hi - lo > 1u) {
            uint mid = lo + ((hi - lo) >> 1);
            int c = 0;
#pragma unroll
            for (int i = 0; i < 8; i++) c += (ub[i] >= mid);
#pragma unroll
            for (int o = 16; o > 0; o >>= 1) c += __shfl_xor_sync(0xFFFFFFFFu, c, o);
            if (lane == 0) atomicAdd(&s_cnt[it], c);
            __syncthreads();
            int tot = s_cnt[it];
            it++;
            if (tot >= TOPK) lo = mid; else hi = mid;
        }
        T = lo;
        {
            int c = 0;
#pragma unroll
            for (int i = 0; i < 8; i++) c += (ub[i] > T);
#pragma unroll
            for (int o = 16; o > 0; o >>= 1) c += __shfl_xor_sync(0xFFFFFFFFu, c, o);
            if (lane == 0) atomicAdd(&s_cnt[33], c);
        }
#pragma unroll
        for (int i = 0; i < 8; i++) {
            if (ub[i] == T) {
                int pos = (i >> 2) * 4096 + tid * 4 + (i & 3);
                int t = atomicAdd(&s_ntie, 1);
                if (t < 64) s_tie[t] = pos;
            }
        }
        __syncthreads();
        int cnt_gt = s_cnt[33];
        int needed = TOPK - cnt_gt;
        int ntie = min(s_ntie, 64);
        if (tid == 0) {
            for (int q = 1; q < ntie; q++) {
                int v = s_tie[q], y = q - 1;
                while (y >= 0 && s_tie[y] > v) { s_tie[y + 1] = s_tie[y]; y--; }
                s_tie[y + 1] = v;
            }
        }
        __syncthreads();
        nsel = min(needed, 64);
    }

    // ---- selection pass ----
    if (phase == 1) {
        // full-row coalesced write: (take ? val : 0) for every element
        float out[8];
#pragma unroll
        for (int i = 0; i < 8; i++) {
            uint u = ub[i];
            int pos = (i >> 2) * 4096 + tid * 4 + (i & 3);
            bool take = (u > T);
            if (u == T) {
                for (int q = 0; q < nsel; q++) take |= (s_tie[q] == pos);
            }
            out[i] = take ? __uint_as_float(u) : 0.0f;
        }
        float4* o4 = (float4*)(full_out + (size_t)b * DIM);
        o4[tid]              = make_float4(out[0], out[1], out[2], out[3]);
        o4[TK_THREADS + tid] = make_float4(out[4], out[5], out[6], out[7]);
    } else {
#pragma unroll
        for (int i = 0; i < 8; i++) {
            uint u = ub[i];
            int pos = (i >> 2) * 4096 + tid * 4 + (i & 3);
            bool take = (u > T);
            if (u == T) {
                for (int q = 0; q < nsel; q++) take |= (s_tie[q] == pos);
            }
            if (take) {
                int slot = atomicAdd(&s_slot, 1);
                s_outv[slot] = __uint_as_float(u);
                s_outi[slot] = pos;
            }
        }
        __syncthreads();
        if (tid < TOPK) {
            int my_i = s_outi[tid];
            float my_v = s_outv[tid];
            int rank = 0;
#pragma unroll 10
            for (int q = 0; q < TOPK; q++) rank += (s_outi[q] < my_i);
            g_vals[b * 64 + rank] = my_v;
            g_idxs[b * 64 + rank] = my_i;
        } else if (tid < 64) {                 // pad entries: val 0, col 0
            g_vals[b * 64 + tid] = 0.0f;
            g_idxs[b * 64 + tid] = 0;
        }
    }
}

// ---------------- kernel 3: sparse GEMV, per-batch sorted sweep ----------------
__global__ __launch_bounds__(256) void gemv_sparse_kernel(const float* __restrict__ syn) {
    int tid  = threadIdx.x;
    int w    = tid >> 5;
    int lane = tid & 31;
    int j = blockIdx.x * 8 + w;

    __shared__ float sv[BATCH][64];
    __shared__ int   si[BATCH][64];

    cudaTriggerProgrammaticLaunchCompletion();     // let topk1 spin up
    cudaGridDependencySynchronize();               // topk0 results visible

    for (int t = tid; t < BATCH * 64; t += 256) {
        sv[t >> 6][t & 63] = g_vals[t];
        si[t >> 6][t & 63] = g_idxs[t];
    }
    __syncthreads();

    const float* __restrict__ row = syn + (size_t)j * DIM;
    float acc[BATCH];
#pragma unroll
    for (int b = 0; b < BATCH; b++) {
        acc[b] = sv[b][lane]      * __ldg(&row[si[b][lane]])
               + sv[b][lane + 32] * __ldg(&row[si[b][lane + 32]]);
    }

#pragma unroll
    for (int o = 16; o > 0; o >>= 1) {
#pragma unroll
        for (int b = 0; b < BATCH; b++) {
            acc[b] += __shfl_down_sync(0xFFFFFFFFu, acc[b], o);
        }
    }
    float mine = 0.0f;
#pragma unroll
    for (int b = 0; b < BATCH; b++) {
        float r = __shfl_sync(0xFFFFFFFFu, acc[b], 0);
        if (lane == b) mine = r;
    }
    if (lane < BATCH) {
        g_z2[(size_t)lane * DIM + j] = sigmoidf(mine);
    }
}

// ---------------- launch ----------------
extern "C" void kernel_launch(void* const* d_in, const int* in_sizes, int n_in,
                              void* d_out, int out_size) {
    const float* sdr = (const float*)d_in[0];   // [8, 8192]
    const float* syn = (const float*)d_in[1];   // [8192, 8192]
    float* out = (float*)d_out;                 // [8, 8192]
    (void)in_sizes; (void)n_in; (void)out_size;

    static int smem_set = 0;
    if (!smem_set) {
        cudaFuncSetAttribute(gemv_dense_kernel,
                             cudaFuncAttributeMaxDynamicSharedMemorySize, DENSE_SMEM);
        smem_set = 1;
    }

    cudaLaunchAttribute pdl[1];
    pdl[0].id = cudaLaunchAttributeProgrammaticStreamSerialization;
    pdl[0].val.programmaticStreamSerializationAllowed = 1;

    {   // dense GEMV
        cudaLaunchConfig_t cfg = {};
        cfg.gridDim = dim3(DIM / 32, 1, 1);
        cfg.blockDim = dim3(256, 1, 1);
        cfg.dynamicSmemBytes = DENSE_SMEM;
        cfg.attrs = pdl; cfg.numAttrs = 1;
        cudaLaunchKernelEx(&cfg, gemv_dense_kernel, syn, sdr);
    }
    {   // topk phase 0
        cudaLaunchConfig_t cfg = {};
        cfg.gridDim = dim3(BATCH, 1, 1);
        cfg.blockDim = dim3(TK_THREADS, 1, 1);
        cfg.attrs = pdl; cfg.numAttrs = 1;
        cudaLaunchKernelEx(&cfg, topk_kernel, out, 0);
    }
    {   // sparse GEMV
        cudaLaunchConfig_t cfg = {};
        cfg.gridDim = dim3(DIM / 8, 1, 1);
        cfg.blockDim = dim3(256, 1, 1);
        cfg.attrs = pdl; cfg.numAttrs = 1;
        cudaLaunchKernelEx(&cfg, gemv_sparse_kernel, syn);
    }
    {   // topk phase 1
        cudaLaunchConfig_t cfg = {};
        cfg.gridDim = dim3(BATCH, 1, 1);
        cfg.blockDim = dim3(TK_THREADS, 1, 1);
        cfg.attrs = pdl; cfg.numAttrs = 1;
        cudaLaunchKernelEx(&cfg, topk_kernel, out, 1);
    }
}